// round 13
// baseline (speedup 1.0000x reference)
#include <cuda_runtime.h>
#include <math.h>

#define BB 4
#define LL 2048
#define KK 30
#define NODEF 128
#define EDGEF 128
#define NEDGE (BB*LL*KK)

// ---- scratch (static device memory) ----
__device__ int    g_idx[NEDGE];
__device__ float  g_Dnb[NEDGE];
__device__ float  g_O[BB*LL*9];          // per node frame, [comp*3 + vec]
__device__ float4 g_Ca4[BB*LL];          // packed Ca coords
__device__ float4 g_posproj[65*32];      // (Wpe[d]+bpe) @ We[0:16]   -> [65][128]
__device__ float4 g_chainproj[2*32];     // (Wch[s]+bch) @ We[39:55]  -> [2][128]
__device__ unsigned long long g_featp[NEDGE*24]; // per-edge features, f32x2-duplicated
__device__ int    g_edd[NEDGE];          // dd | (same<<8)

__device__ __forceinline__ float sgnf(float x) {
    return (x > 0.f) ? 1.f : ((x < 0.f) ? -1.f : 0.f);
}
__device__ __forceinline__ float clampf(float x, float lo, float hi) {
    return fminf(fmaxf(x, lo), hi);
}

// packed f32x2 helpers
__device__ __forceinline__ unsigned long long fma2(unsigned long long a,
        unsigned long long b, unsigned long long c) {
    unsigned long long d;
    asm("fma.rn.f32x2 %0, %1, %2, %3;" : "=l"(d) : "l"(a), "l"(b), "l"(c));
    return d;
}
__device__ __forceinline__ unsigned long long add2(unsigned long long a,
        unsigned long long b) {
    unsigned long long d;
    asm("add.rn.f32x2 %0, %1, %2;" : "=l"(d) : "l"(a), "l"(b));
    return d;
}
__device__ __forceinline__ unsigned long long pack2(float lo, float hi) {
    unsigned long long d;
    unsigned a = __float_as_uint(lo), b = __float_as_uint(hi);
    asm("mov.b64 %0, {%1, %2};" : "=l"(d) : "r"(a), "r"(b));
    return d;
}
__device__ __forceinline__ void unpack2(unsigned long long v, float& lo, float& hi) {
    unsigned a, b;
    asm("mov.b64 {%0, %1}, %2;" : "=r"(a), "=r"(b) : "l"(v));
    lo = __uint_as_float(a); hi = __uint_as_float(b);
}

// ============================================================
// Kernel P: pack Ca into float4
// ============================================================
__global__ void __launch_bounds__(256) pack_kernel(const float* __restrict__ X) {
    int n = blockIdx.x * 256 + threadIdx.x;
    if (n < BB*LL) {
        g_Ca4[n] = make_float4(X[n*12+3], X[n*12+4], X[n*12+5], 0.f);
    }
}

// ============================================================
// Kernel Q: precompute positional / chain projections
// ============================================================
__global__ void __launch_bounds__(128) proj_kernel(
        const float* __restrict__ Wpe, const float* __restrict__ bpe,
        const float* __restrict__ Wch, const float* __restrict__ bch,
        const float* __restrict__ We) {
    int ch = threadIdx.x;
    if (blockIdx.x < 65) {
        int d = blockIdx.x;
        float acc = 0.f;
        #pragma unroll
        for (int t = 0; t < 16; t++)
            acc = fmaf(Wpe[d*16 + t] + bpe[t], We[t*EDGEF + ch], acc);
        ((float*)g_posproj)[d*EDGEF + ch] = acc;
    } else {
        int s = blockIdx.x - 65;
        float acc = 0.f;
        #pragma unroll
        for (int t = 0; t < 16; t++)
            acc = fmaf(Wch[s*16 + t] + bch[t], We[(39 + t)*EDGEF + ch], acc);
        ((float*)g_chainproj)[s*EDGEF + ch] = acc;
    }
}

// ============================================================
// Kernel A: top-30 NN. 8 queries/block; Ca staged in smem.
// Selection runs on RAW d^2 bits (sqrt is monotone -> same ordering at
// bin granularity); sqrt applied ONLY to ~35 candidates per query.
// Final keys (sqrt_bits<<32|j) reproduce jax.lax.top_k ordering exactly.
// ============================================================
#define QPB 8
__global__ void __launch_bounds__(256) topk_kernel(float* __restrict__ outIdxF) {
    __shared__ float4 sCa[LL];                 // 32 KB
    __shared__ unsigned long long cand[1024];  // 8 KB
    __shared__ unsigned warpsums[2][8];
    __shared__ unsigned scnt;

    const int node0 = blockIdx.x * QPB;
    const int b = node0 >> 11;
    const int tid = threadIdx.x;
    const int wid = tid >> 5;

    const float4* __restrict__ base = g_Ca4 + b*LL;
    #pragma unroll
    for (int u = 0; u < LL/256; u++) sCa[tid + 256*u] = base[tid + 256*u];
    __syncthreads();

    for (int q = 0; q < QPB; q++) {
        const int node = node0 + q;
        const int qi = node & (LL - 1);
        if (tid == 0) scnt = 0;

        // squared distances only (exact reference op order: mul, add, add)
        const float4 ci = sCa[qi];
        unsigned bt[8];
        #pragma unroll
        for (int u = 0; u < 8; u++) {
            float4 cj = sCa[tid + 256*u];
            float dx = ci.x - cj.x, dy = ci.y - cj.y, dz = ci.z - cj.z;
            float d2 = __fadd_rn(__fadd_rn(__fmul_rn(dx,dx), __fmul_rn(dy,dy)), __fmul_rn(dz,dz));
            bt[u] = __float_as_uint(d2);
        }

        // binary search: smallest B with count(d2bits < (B+1)<<20) >= 30
        unsigned lo = 0, hi = 2047;
        #pragma unroll
        for (int it = 0; it < 11; it++) {
            unsigned mid = (lo + hi) >> 1;
            unsigned thr = (mid + 1u) << 20;
            unsigned c = 0;
            #pragma unroll
            for (int u = 0; u < 8; u++) c += (bt[u] < thr) ? 1u : 0u;
            c = __reduce_add_sync(0xffffffffu, c);
            if ((tid & 31) == 0) warpsums[it & 1][wid] = c;
            __syncthreads();
            unsigned tot = 0;
            #pragma unroll
            for (int w = 0; w < 8; w++) tot += warpsums[it & 1][w];
            if (tot >= KK) hi = mid; else lo = mid + 1;
        }
        const unsigned thrB = (lo + 1u) << 20;

        // collect candidates; sqrt ONLY here (~35 per query), bit-exact:
        // d = sqrt(d2 + 1e-6) with d2 in reference op order
        #pragma unroll
        for (int u = 0; u < 8; u++) {
            if (bt[u] < thrB) {
                unsigned p = atomicAdd(&scnt, 1);
                if (p < 1024) {
                    float d = __fsqrt_rn(__fadd_rn(__uint_as_float(bt[u]), 1e-6f));
                    cand[p] = ((unsigned long long)__float_as_uint(d) << 32)
                            | (unsigned)(tid + 256*u);
                }
            }
        }
        __syncthreads();

        // exact rank sort (u64 keys unique -> ranks unique)
        const int c = (int)(scnt < 1024u ? scnt : 1024u);
        for (int idx = tid; idx < c; idx += 256) {
            unsigned long long k = cand[idx];
            int r = 0;
            for (int m = 0; m < c; m++) r += (cand[m] < k) ? 1 : 0;
            if (r < KK) {
                int j = (int)(k & 0xffffffffu);
                g_idx[node*KK + r] = j;
                g_Dnb[node*KK + r] = __uint_as_float((unsigned)(k >> 32));
                outIdxF[node*KK + r] = (float)j;
            }
        }
        __syncthreads();   // protect cand/scnt reuse next query
    }
}

// ============================================================
// Kernel B: per-node O frame + AD features -> V (LN). 1 warp / node.
// ============================================================
__global__ void __launch_bounds__(128) node_kernel(const float* __restrict__ X,
        const float* __restrict__ Wn, const float* __restrict__ bnod,
        const float* __restrict__ gn, const float* __restrict__ bnn,
        float* __restrict__ outV) {
    const int warp = threadIdx.x >> 5;
    const int lane = threadIdx.x & 31;
    const int node = blockIdx.x * 4 + warp;
    const int b = node >> 11;
    const int i = node & (LL - 1);
    const float* Xb = X + (size_t)b * LL * 12;

    float ad0 = 0.f, ad1 = 0.f, ad2 = 0.f;
    if (lane == 0) {
        float Nx = Xb[i*12+0], Ny = Xb[i*12+1], Nz = Xb[i*12+2];
        float Ax = Xb[i*12+3], Ay = Xb[i*12+4], Az = Xb[i*12+5];
        float Cx = Xb[i*12+6], Cy = Xb[i*12+7], Cz = Xb[i*12+8];
        float v1x = Nx-Ax, v1y = Ny-Ay, v1z = Nz-Az;
        float n1 = sqrtf(v1x*v1x + v1y*v1y + v1z*v1z) + 1e-6f;
        float e1x = v1x/n1, e1y = v1y/n1, e1z = v1z/n1;
        float v2x = Cx-Ax, v2y = Cy-Ay, v2z = Cz-Az;
        float dp = e1x*v2x + e1y*v2y + e1z*v2z;
        float u2x = v2x - dp*e1x, u2y = v2y - dp*e1y, u2z = v2z - dp*e1z;
        float n2 = sqrtf(u2x*u2x + u2y*u2y + u2z*u2z) + 1e-6f;
        float e2x = u2x/n2, e2y = u2y/n2, e2z = u2z/n2;
        float e3x = e1y*e2z - e1z*e2y;
        float e3y = e1z*e2x - e1x*e2z;
        float e3z = e1x*e2y - e1y*e2x;
        float* O = &g_O[(size_t)node*9];
        O[0]=e1x; O[1]=e2x; O[2]=e3x;
        O[3]=e1y; O[4]=e2y; O[5]=e3y;
        O[6]=e1z; O[7]=e2z; O[8]=e3z;

        if (i >= 1 && i <= LL - 3) {
            float p0x=Xb[(i-1)*12+3], p0y=Xb[(i-1)*12+4], p0z=Xb[(i-1)*12+5];
            float p2x=Xb[(i+1)*12+3], p2y=Xb[(i+1)*12+4], p2z=Xb[(i+1)*12+5];
            float p3x=Xb[(i+2)*12+3], p3y=Xb[(i+2)*12+4], p3z=Xb[(i+2)*12+5];
            float ax=Ax-p0x, ay=Ay-p0y, az=Az-p0z;
            float bx=p2x-Ax, by=p2y-Ay, bz=p2z-Az;
            float cx=p3x-p2x, cy=p3y-p2y, cz=p3z-p2z;
            float na = fmaxf(sqrtf(ax*ax+ay*ay+az*az), 1e-12f);
            float nb = fmaxf(sqrtf(bx*bx+by*by+bz*bz), 1e-12f);
            float nc = fmaxf(sqrtf(cx*cx+cy*cy+cz*cz), 1e-12f);
            float u2x_=ax/na, u2y_=ay/na, u2z_=az/na;
            float u1x_=bx/nb, u1y_=by/nb, u1z_=bz/nb;
            float u0x_=cx/nc, u0y_=cy/nc, u0z_=cz/nc;
            float c2x = u2y_*u1z_ - u2z_*u1y_;
            float c2y = u2z_*u1x_ - u2x_*u1z_;
            float c2z = u2x_*u1y_ - u2y_*u1x_;
            float c1x = u1y_*u0z_ - u1z_*u0y_;
            float c1y = u1z_*u0x_ - u1x_*u0z_;
            float c1z = u1x_*u0y_ - u1y_*u0x_;
            float nn2 = fmaxf(sqrtf(c2x*c2x+c2y*c2y+c2z*c2z), 1e-12f);
            float nn1 = fmaxf(sqrtf(c1x*c1x+c1y*c1y+c1z*c1z), 1e-12f);
            c2x/=nn2; c2y/=nn2; c2z/=nn2;
            c1x/=nn1; c1y/=nn1; c1z/=nn1;
            float cosA = clampf(-(u1x_*u0x_ + u1y_*u0y_ + u1z_*u0z_), -1.f+1e-6f, 1.f-1e-6f);
            float A = acosf(cosA);
            float cosD = clampf(c2x*c1x + c2y*c1y + c2z*c1z, -1.f+1e-6f, 1.f-1e-6f);
            float sg = sgnf(u2x_*c1x + u2y_*c1y + u2z_*c1z);
            float D = sg * acosf(cosD);
            ad0 = cosf(A);
            ad1 = sinf(A) * cosf(D);
            ad2 = sinf(A) * sinf(D);
        }
    }
    ad0 = __shfl_sync(0xffffffffu, ad0, 0);
    ad1 = __shfl_sync(0xffffffffu, ad1, 0);
    ad2 = __shfl_sync(0xffffffffu, ad2, 0);

    const float4 w0 = ((const float4*)Wn)[lane];
    const float4 w1 = ((const float4*)Wn)[32 + lane];
    const float4 w2 = ((const float4*)Wn)[64 + lane];
    const float4 b4 = ((const float4*)bnod)[lane];
    float x0 = b4.x + ad0*w0.x + ad1*w1.x + ad2*w2.x;
    float x1 = b4.y + ad0*w0.y + ad1*w1.y + ad2*w2.y;
    float x2 = b4.z + ad0*w0.z + ad1*w1.z + ad2*w2.z;
    float x3 = b4.w + ad0*w0.w + ad1*w1.w + ad2*w2.w;

    float sum = x0 + x1 + x2 + x3;
    #pragma unroll
    for (int o = 16; o > 0; o >>= 1) sum += __shfl_xor_sync(0xffffffffu, sum, o);
    float mean = sum * (1.0f/NODEF);
    float d0 = x0-mean, d1 = x1-mean, d2 = x2-mean, d3 = x3-mean;
    float vs = d0*d0 + d1*d1 + d2*d2 + d3*d3;
    #pragma unroll
    for (int o = 16; o > 0; o >>= 1) vs += __shfl_xor_sync(0xffffffffu, vs, o);
    float inv = 1.0f / sqrtf(vs * (1.0f/NODEF) + 1e-5f);
    const float4 g4 = ((const float4*)gn)[lane];
    const float4 bb4 = ((const float4*)bnn)[lane];
    float4 y;
    y.x = d0*inv*g4.x + bb4.x;
    y.y = d1*inv*g4.y + bb4.y;
    y.z = d2*inv*g4.z + bb4.z;
    y.w = d3*inv*g4.w + bb4.w;
    ((float4*)outV)[(size_t)node*32 + lane] = y;
}

// ============================================================
// Kernel G: per-edge geometry + RBF, one thread per edge.
// Emits features pre-packed as duplicated f32x2 (u64) for the edge matvec.
// ============================================================
__global__ void __launch_bounds__(256) geom_kernel(const int* __restrict__ res,
                                                   const int* __restrict__ chn) {
    const int e = blockIdx.x * 256 + threadIdx.x;
    if (e >= NEDGE) return;
    const int node = e / KK;
    const int b = node >> 11;
    const int j = g_idx[e];
    const int nj = b*LL + j;

    float Oi[9], Oj[9];
    #pragma unroll
    for (int q = 0; q < 9; q++) Oi[q] = g_O[(size_t)node*9 + q];
    #pragma unroll
    for (int q = 0; q < 9; q++) Oj[q] = g_O[(size_t)nj*9 + q];
    const float4 ci = g_Ca4[node];
    const float4 cj = g_Ca4[nj];

    unsigned long long* F = &g_featp[(size_t)e*24];

    const float Dv = g_Dnb[e];
    #pragma unroll
    for (int t = 0; t < 16; t++) {
        float mu = 2.0f + (20.0f/15.0f) * (float)t;
        float z = (Dv - mu) / 1.25f;
        float v = expf(-(z*z));
        F[t] = pack2(v, v);
    }

    float dX0 = cj.x - ci.x, dX1 = cj.y - ci.y, dX2 = cj.z - ci.z;
    float du0 = Oi[0]*dX0 + Oi[1]*dX1 + Oi[2]*dX2;
    float du1 = Oi[3]*dX0 + Oi[4]*dX1 + Oi[5]*dX2;
    float du2 = Oi[6]*dX0 + Oi[7]*dX1 + Oi[8]*dX2;
    float nn = fmaxf(sqrtf(du0*du0 + du1*du1 + du2*du2), 1e-12f);
    du0 /= nn; du1 /= nn; du2 /= nn;
    F[16] = pack2(du0, du0); F[17] = pack2(du1, du1); F[18] = pack2(du2, du2);

    float R[3][3];
    #pragma unroll
    for (int ii = 0; ii < 3; ii++)
        #pragma unroll
        for (int mm = 0; mm < 3; mm++)
            R[ii][mm] = Oi[0*3+ii]*Oj[0*3+mm] + Oi[1*3+ii]*Oj[1*3+mm] + Oi[2*3+ii]*Oj[2*3+mm];
    float mx = 0.5f * sqrtf(fabsf(1.f + R[0][0] - R[1][1] - R[2][2]));
    float my = 0.5f * sqrtf(fabsf(1.f - R[0][0] + R[1][1] - R[2][2]));
    float mz = 0.5f * sqrtf(fabsf(1.f - R[0][0] - R[1][1] + R[2][2]));
    float qx = sgnf(R[2][1] - R[1][2]) * mx;
    float qy = sgnf(R[0][2] - R[2][0]) * my;
    float qz = sgnf(R[1][0] - R[0][1]) * mz;
    float qw = sqrtf(fmaxf(1.f + R[0][0] + R[1][1] + R[2][2], 0.f)) * 0.5f;
    float qn = fmaxf(sqrtf(qx*qx + qy*qy + qz*qz + qw*qw), 1e-12f);
    qx /= qn; qy /= qn; qz /= qn; qw /= qn;
    F[19] = pack2(qx, qx); F[20] = pack2(qy, qy);
    F[21] = pack2(qz, qz); F[22] = pack2(qw, qw);
    F[23] = 0ull;

    int dd = res[nj] - res[node] + 32;
    dd = dd < 0 ? 0 : (dd > 64 ? 64 : dd);
    int same = (chn[nj] == chn[node]) ? 1 : 0;
    g_edd[e] = dd | (same << 8);
}

// ============================================================
// Kernel C: edges. 1 warp / node. Weights in registers (f32x2);
// features staged per-edge into smem (pre-packed u64, LDS broadcast).
// Inner loop = 23 x (LDS.64 + 2 FFMA2); no shuffles until LN.
// ============================================================
__global__ void __launch_bounds__(128) edge_kernel(
        const float* __restrict__ We,  const float* __restrict__ be,
        const float* __restrict__ ge,  const float* __restrict__ bne,
        float* __restrict__ outE) {
    __shared__ unsigned long long sfp[4][24];

    const int tid = threadIdx.x;
    const int warp = tid >> 5;
    const int lane = tid & 31;
    const int node = blockIdx.x * 4 + warp;

    // stage weight rows 16..38 into registers (this lane's 4 channels)
    unsigned long long wlo[23], whi[23];
    #pragma unroll
    for (int f = 0; f < 23; f++) {
        ulonglong2 wv = ((const ulonglong2*)(We + (16 + f)*EDGEF))[lane];
        wlo[f] = wv.x; whi[f] = wv.y;
    }
    const float4 bec  = ((const float4*)be)[lane];
    const float4 gec  = ((const float4*)ge)[lane];
    const float4 bnec = ((const float4*)bne)[lane];
    const unsigned long long bec01 = pack2(bec.x, bec.y);
    const unsigned long long bec23 = pack2(bec.z, bec.w);

    for (int k = 0; k < KK; k++) {
        const int e = node*KK + k;
        if (lane < 24) sfp[warp][lane] = g_featp[(size_t)e*24 + lane];
        const int edd = g_edd[e];
        const int dd = edd & 255;
        const int same = (edd >> 8) & 1;

        ulonglong2 pp = ((const ulonglong2*)g_posproj)[dd*32 + lane];
        ulonglong2 cp = ((const ulonglong2*)g_chainproj)[(same ? 0 : 32) + lane];
        unsigned long long ax = add2(add2(bec01, pp.x), cp.x);
        unsigned long long ay = add2(add2(bec23, pp.y), cp.y);
        __syncwarp();

        #pragma unroll
        for (int f = 0; f < 23; f++) {
            unsigned long long sp = sfp[warp][f];
            ax = fma2(sp, wlo[f], ax);
            ay = fma2(sp, whi[f], ay);
        }
        __syncwarp();   // sfp reuse next iteration

        float x0, x1, x2, x3;
        unpack2(ax, x0, x1);
        unpack2(ay, x2, x3);

        float sum = x0 + x1 + x2 + x3;
        #pragma unroll
        for (int o = 16; o > 0; o >>= 1) sum += __shfl_xor_sync(0xffffffffu, sum, o);
        float mean = sum * (1.0f/EDGEF);
        float d0 = x0-mean, d1 = x1-mean, d2 = x2-mean, d3 = x3-mean;
        float vs = d0*d0 + d1*d1 + d2*d2 + d3*d3;
        #pragma unroll
        for (int o = 16; o > 0; o >>= 1) vs += __shfl_xor_sync(0xffffffffu, vs, o);
        float inv = 1.0f / sqrtf(vs * (1.0f/EDGEF) + 1e-5f);
        float4 y;
        y.x = d0*inv*gec.x + bnec.x;
        y.y = d1*inv*gec.y + bnec.y;
        y.z = d2*inv*gec.z + bnec.z;
        y.w = d3*inv*gec.w + bnec.w;
        ((float4*)outE)[(size_t)e*32 + lane] = y;
    }
}

// ============================================================
extern "C" void kernel_launch(void* const* d_in, const int* in_sizes, int n_in,
                              void* d_out, int out_size) {
    const float* X    = (const float*)d_in[0];
    const int*   res  = (const int*)d_in[2];
    const int*   chn  = (const int*)d_in[3];
    const float* Wpe  = (const float*)d_in[4];
    const float* bpe  = (const float*)d_in[5];
    const float* Wch  = (const float*)d_in[6];
    const float* bch  = (const float*)d_in[7];
    const float* Wn   = (const float*)d_in[8];
    const float* bn   = (const float*)d_in[9];
    const float* We   = (const float*)d_in[10];
    const float* be   = (const float*)d_in[11];
    const float* gn   = (const float*)d_in[12];
    const float* bnn  = (const float*)d_in[13];
    const float* gE   = (const float*)d_in[14];
    const float* bnE  = (const float*)d_in[15];

    float* out = (float*)d_out;
    const size_t VSZ = (size_t)BB*LL*NODEF;       // 1,048,576
    const size_t ESZ = (size_t)BB*LL*KK*EDGEF;    // 31,457,280
    float* outV    = out;
    float* outE    = out + VSZ;
    float* outIdxF = out + VSZ + ESZ;

    // order chosen so the ncu capture slot (cycle index 3) lands on topk
    pack_kernel<<<(BB*LL + 255)/256, 256>>>(X);
    proj_kernel<<<67, 128>>>(Wpe, bpe, Wch, bch, We);
    node_kernel<<<BB*LL/4, 128>>>(X, Wn, bn, gn, bnn, outV);
    topk_kernel<<<BB*LL/QPB, 256>>>(outIdxF);
    geom_kernel<<<(NEDGE + 255)/256, 256>>>(res, chn);
    edge_kernel<<<BB*LL/4, 128>>>(We, be, gE, bnE, outE);
}

// round 15
// speedup vs baseline: 1.4581x; 1.4581x over previous
#include <cuda_runtime.h>
#include <math.h>

#define BB 4
#define LL 2048
#define KK 30
#define NODEF 128
#define EDGEF 128
#define NEDGE (BB*LL*KK)

// ---- scratch (static device memory) ----
__device__ int    g_idx[NEDGE];
__device__ float  g_Dnb[NEDGE];
__device__ float  g_O[BB*LL*9];          // per node frame, [comp*3 + vec]
__device__ float4 g_Ca4[BB*LL];          // packed Ca coords
__device__ float4 g_posproj[65*32];      // (Wpe[d]+bpe) @ We[0:16]   -> [65][128]
__device__ float4 g_chainproj[2*32];     // (Wch[s]+bch) @ We[39:55]  -> [2][128]

__device__ __forceinline__ float sgnf(float x) {
    return (x > 0.f) ? 1.f : ((x < 0.f) ? -1.f : 0.f);
}
__device__ __forceinline__ float clampf(float x, float lo, float hi) {
    return fminf(fmaxf(x, lo), hi);
}

// packed f32x2 helpers
__device__ __forceinline__ unsigned long long fma2(unsigned long long a,
        unsigned long long b, unsigned long long c) {
    unsigned long long d;
    asm("fma.rn.f32x2 %0, %1, %2, %3;" : "=l"(d) : "l"(a), "l"(b), "l"(c));
    return d;
}
__device__ __forceinline__ unsigned long long add2(unsigned long long a,
        unsigned long long b) {
    unsigned long long d;
    asm("add.rn.f32x2 %0, %1, %2;" : "=l"(d) : "l"(a), "l"(b));
    return d;
}
__device__ __forceinline__ unsigned long long pack2(float lo, float hi) {
    unsigned long long d;
    unsigned a = __float_as_uint(lo), b = __float_as_uint(hi);
    asm("mov.b64 %0, {%1, %2};" : "=l"(d) : "r"(a), "r"(b));
    return d;
}
__device__ __forceinline__ void unpack2(unsigned long long v, float& lo, float& hi) {
    unsigned a, b;
    asm("mov.b64 {%0, %1}, %2;" : "=r"(a), "=r"(b) : "l"(v));
    lo = __uint_as_float(a); hi = __uint_as_float(b);
}

// ============================================================
// Kernel P: pack Ca into float4
// ============================================================
__global__ void __launch_bounds__(256) pack_kernel(const float* __restrict__ X) {
    int n = blockIdx.x * 256 + threadIdx.x;
    if (n < BB*LL) {
        g_Ca4[n] = make_float4(X[n*12+3], X[n*12+4], X[n*12+5], 0.f);
    }
}

// ============================================================
// Kernel Q: precompute positional / chain projections
// ============================================================
__global__ void __launch_bounds__(128) proj_kernel(
        const float* __restrict__ Wpe, const float* __restrict__ bpe,
        const float* __restrict__ Wch, const float* __restrict__ bch,
        const float* __restrict__ We) {
    int ch = threadIdx.x;
    if (blockIdx.x < 65) {
        int d = blockIdx.x;
        float acc = 0.f;
        #pragma unroll
        for (int t = 0; t < 16; t++)
            acc = fmaf(Wpe[d*16 + t] + bpe[t], We[t*EDGEF + ch], acc);
        ((float*)g_posproj)[d*EDGEF + ch] = acc;
    } else {
        int s = blockIdx.x - 65;
        float acc = 0.f;
        #pragma unroll
        for (int t = 0; t < 16; t++)
            acc = fmaf(Wch[s*16 + t] + bch[t], We[(39 + t)*EDGEF + ch], acc);
        ((float*)g_chainproj)[s*EDGEF + ch] = acc;
    }
}

// ============================================================
// Kernel A: top-30 NN, ONE WARP PER QUERY (no block barriers in search).
// 8 queries/block; Ca staged in smem once. Selection on raw d^2 bits
// (sqrt monotone); sqrt only on ~35 candidates. Keys (sqrt_bits<<32|j)
// reproduce jax.lax.top_k ordering exactly.
// ============================================================
#define QPB 8
#define CANDW 384
__global__ void __launch_bounds__(256) topk_kernel(float* __restrict__ outIdxF) {
    __shared__ float4 sCa[LL];                       // 32 KB
    __shared__ unsigned long long cand[QPB][CANDW];  // 24 KB
    __shared__ unsigned scnt[QPB];

    const int node0 = blockIdx.x * QPB;
    const int b = node0 >> 11;
    const int tid = threadIdx.x;
    const int w = tid >> 5;
    const int lane = tid & 31;

    const float4* __restrict__ base = g_Ca4 + b*LL;
    #pragma unroll
    for (int u = 0; u < LL/256; u++) sCa[tid + 256*u] = base[tid + 256*u];
    if (lane == 0) scnt[w] = 0;
    __syncthreads();

    const int node = node0 + w;
    const int qi = node & (LL - 1);

    // squared distances (exact reference op order: mul, add, add)
    const float4 ci = sCa[qi];
    unsigned bt[64];
    #pragma unroll
    for (int u = 0; u < 64; u++) {
        float4 cj = sCa[u*32 + lane];
        float dx = ci.x - cj.x, dy = ci.y - cj.y, dz = ci.z - cj.z;
        float d2 = __fadd_rn(__fadd_rn(__fmul_rn(dx,dx), __fmul_rn(dy,dy)), __fmul_rn(dz,dz));
        bt[u] = __float_as_uint(d2);
    }

    // warp-local binary search: smallest B with count(d2bits < (B+1)<<20) >= 30
    unsigned lo = 0, hi = 2047;
    for (int it = 0; it < 11; it++) {
        unsigned mid = (lo + hi) >> 1;
        unsigned thr = (mid + 1u) << 20;
        unsigned c = 0;
        #pragma unroll
        for (int u = 0; u < 64; u++) c += (bt[u] < thr) ? 1u : 0u;
        c = __reduce_add_sync(0xffffffffu, c);
        if (c >= KK) hi = mid; else lo = mid + 1;
    }
    const unsigned thrB = (lo + 1u) << 20;

    // collect candidates; sqrt only here (bit-exact: sqrt(d2 + 1e-6))
    #pragma unroll
    for (int u = 0; u < 64; u++) {
        if (bt[u] < thrB) {
            unsigned p = atomicAdd(&scnt[w], 1);
            if (p < CANDW) {
                float d = __fsqrt_rn(__fadd_rn(__uint_as_float(bt[u]), 1e-6f));
                cand[w][p] = ((unsigned long long)__float_as_uint(d) << 32)
                           | (unsigned)(u*32 + lane);
            }
        }
    }
    __syncwarp();

    // exact rank sort (u64 keys unique -> ranks unique)
    const int c = (int)(scnt[w] < (unsigned)CANDW ? scnt[w] : (unsigned)CANDW);
    for (int idx = lane; idx < c; idx += 32) {
        unsigned long long k = cand[w][idx];
        int r = 0;
        for (int m = 0; m < c; m++) r += (cand[w][m] < k) ? 1 : 0;
        if (r < KK) {
            int j = (int)(k & 0xffffffffu);
            g_idx[node*KK + r] = j;
            g_Dnb[node*KK + r] = __uint_as_float((unsigned)(k >> 32));
            outIdxF[node*KK + r] = (float)j;
        }
    }
}

// ============================================================
// Kernel B: per-node O frame + AD features -> V (LN). 1 warp / node.
// ============================================================
__global__ void __launch_bounds__(128) node_kernel(const float* __restrict__ X,
        const float* __restrict__ Wn, const float* __restrict__ bnod,
        const float* __restrict__ gn, const float* __restrict__ bnn,
        float* __restrict__ outV) {
    const int warp = threadIdx.x >> 5;
    const int lane = threadIdx.x & 31;
    const int node = blockIdx.x * 4 + warp;
    const int b = node >> 11;
    const int i = node & (LL - 1);
    const float* Xb = X + (size_t)b * LL * 12;

    float ad0 = 0.f, ad1 = 0.f, ad2 = 0.f;
    if (lane == 0) {
        float Nx = Xb[i*12+0], Ny = Xb[i*12+1], Nz = Xb[i*12+2];
        float Ax = Xb[i*12+3], Ay = Xb[i*12+4], Az = Xb[i*12+5];
        float Cx = Xb[i*12+6], Cy = Xb[i*12+7], Cz = Xb[i*12+8];
        float v1x = Nx-Ax, v1y = Ny-Ay, v1z = Nz-Az;
        float n1 = sqrtf(v1x*v1x + v1y*v1y + v1z*v1z) + 1e-6f;
        float e1x = v1x/n1, e1y = v1y/n1, e1z = v1z/n1;
        float v2x = Cx-Ax, v2y = Cy-Ay, v2z = Cz-Az;
        float dp = e1x*v2x + e1y*v2y + e1z*v2z;
        float u2x = v2x - dp*e1x, u2y = v2y - dp*e1y, u2z = v2z - dp*e1z;
        float n2 = sqrtf(u2x*u2x + u2y*u2y + u2z*u2z) + 1e-6f;
        float e2x = u2x/n2, e2y = u2y/n2, e2z = u2z/n2;
        float e3x = e1y*e2z - e1z*e2y;
        float e3y = e1z*e2x - e1x*e2z;
        float e3z = e1x*e2y - e1y*e2x;
        float* O = &g_O[(size_t)node*9];
        O[0]=e1x; O[1]=e2x; O[2]=e3x;
        O[3]=e1y; O[4]=e2y; O[5]=e3y;
        O[6]=e1z; O[7]=e2z; O[8]=e3z;

        if (i >= 1 && i <= LL - 3) {
            float p0x=Xb[(i-1)*12+3], p0y=Xb[(i-1)*12+4], p0z=Xb[(i-1)*12+5];
            float p2x=Xb[(i+1)*12+3], p2y=Xb[(i+1)*12+4], p2z=Xb[(i+1)*12+5];
            float p3x=Xb[(i+2)*12+3], p3y=Xb[(i+2)*12+4], p3z=Xb[(i+2)*12+5];
            float ax=Ax-p0x, ay=Ay-p0y, az=Az-p0z;
            float bx=p2x-Ax, by=p2y-Ay, bz=p2z-Az;
            float cx=p3x-p2x, cy=p3y-p2y, cz=p3z-p2z;
            float na = fmaxf(sqrtf(ax*ax+ay*ay+az*az), 1e-12f);
            float nb = fmaxf(sqrtf(bx*bx+by*by+bz*bz), 1e-12f);
            float nc = fmaxf(sqrtf(cx*cx+cy*cy+cz*cz), 1e-12f);
            float u2x_=ax/na, u2y_=ay/na, u2z_=az/na;
            float u1x_=bx/nb, u1y_=by/nb, u1z_=bz/nb;
            float u0x_=cx/nc, u0y_=cy/nc, u0z_=cz/nc;
            float c2x = u2y_*u1z_ - u2z_*u1y_;
            float c2y = u2z_*u1x_ - u2x_*u1z_;
            float c2z = u2x_*u1y_ - u2y_*u1x_;
            float c1x = u1y_*u0z_ - u1z_*u0y_;
            float c1y = u1z_*u0x_ - u1x_*u0z_;
            float c1z = u1x_*u0y_ - u1y_*u0x_;
            float nn2 = fmaxf(sqrtf(c2x*c2x+c2y*c2y+c2z*c2z), 1e-12f);
            float nn1 = fmaxf(sqrtf(c1x*c1x+c1y*c1y+c1z*c1z), 1e-12f);
            c2x/=nn2; c2y/=nn2; c2z/=nn2;
            c1x/=nn1; c1y/=nn1; c1z/=nn1;
            float cosA = clampf(-(u1x_*u0x_ + u1y_*u0y_ + u1z_*u0z_), -1.f+1e-6f, 1.f-1e-6f);
            float A = acosf(cosA);
            float cosD = clampf(c2x*c1x + c2y*c1y + c2z*c1z, -1.f+1e-6f, 1.f-1e-6f);
            float sg = sgnf(u2x_*c1x + u2y_*c1y + u2z_*c1z);
            float D = sg * acosf(cosD);
            ad0 = cosf(A);
            ad1 = sinf(A) * cosf(D);
            ad2 = sinf(A) * sinf(D);
        }
    }
    ad0 = __shfl_sync(0xffffffffu, ad0, 0);
    ad1 = __shfl_sync(0xffffffffu, ad1, 0);
    ad2 = __shfl_sync(0xffffffffu, ad2, 0);

    const float4 w0 = ((const float4*)Wn)[lane];
    const float4 w1 = ((const float4*)Wn)[32 + lane];
    const float4 w2 = ((const float4*)Wn)[64 + lane];
    const float4 b4 = ((const float4*)bnod)[lane];
    float x0 = b4.x + ad0*w0.x + ad1*w1.x + ad2*w2.x;
    float x1 = b4.y + ad0*w0.y + ad1*w1.y + ad2*w2.y;
    float x2 = b4.z + ad0*w0.z + ad1*w1.z + ad2*w2.z;
    float x3 = b4.w + ad0*w0.w + ad1*w1.w + ad2*w2.w;

    float sum = x0 + x1 + x2 + x3;
    #pragma unroll
    for (int o = 16; o > 0; o >>= 1) sum += __shfl_xor_sync(0xffffffffu, sum, o);
    float mean = sum * (1.0f/NODEF);
    float d0 = x0-mean, d1 = x1-mean, d2 = x2-mean, d3 = x3-mean;
    float vs = d0*d0 + d1*d1 + d2*d2 + d3*d3;
    #pragma unroll
    for (int o = 16; o > 0; o >>= 1) vs += __shfl_xor_sync(0xffffffffu, vs, o);
    float inv = 1.0f / sqrtf(vs * (1.0f/NODEF) + 1e-5f);
    const float4 g4 = ((const float4*)gn)[lane];
    const float4 bb4 = ((const float4*)bnn)[lane];
    float4 y;
    y.x = d0*inv*g4.x + bb4.x;
    y.y = d1*inv*g4.y + bb4.y;
    y.z = d2*inv*g4.z + bb4.z;
    y.w = d3*inv*g4.w + bb4.w;
    ((float4*)outV)[(size_t)node*32 + lane] = y;
}

// ============================================================
// Kernel C (FUSED geometry + matvec): 1 warp / node, 4 warps / block.
// Phase 1: lanes 0..29 each compute ONE edge's geometry+RBF in parallel,
//          writing f32x2-packed features to smem [feat][k] (broadcast reads).
// Phase 2: 30-iteration matvec with register weights + warp-shuffle LN.
// No global feature round trip.
// ============================================================
__global__ void __launch_bounds__(128, 3) edge_kernel(
        const int* __restrict__ res, const int* __restrict__ chn,
        const float* __restrict__ We,  const float* __restrict__ be,
        const float* __restrict__ ge,  const float* __restrict__ bne,
        float* __restrict__ outE) {
    __shared__ unsigned long long sfp[4][23][32];   // [warp][feat][k]  23.5 KB
    __shared__ int sedd[4][32];

    const int tid = threadIdx.x;
    const int warp = tid >> 5;
    const int lane = tid & 31;
    const int node = blockIdx.x * 4 + warp;
    const int b = node >> 11;

    // ---- phase 1: per-edge geometry, one lane per edge ----
    if (lane < KK) {
        const int e = node*KK + lane;
        const int j = g_idx[e];
        const int nj = b*LL + j;

        float Oi[9], Oj[9];
        #pragma unroll
        for (int q = 0; q < 9; q++) Oi[q] = g_O[(size_t)node*9 + q];
        #pragma unroll
        for (int q = 0; q < 9; q++) Oj[q] = g_O[(size_t)nj*9 + q];
        const float4 ci = g_Ca4[node];
        const float4 cj = g_Ca4[nj];

        const float Dv = g_Dnb[e];
        #pragma unroll
        for (int t = 0; t < 16; t++) {
            float mu = 2.0f + (20.0f/15.0f) * (float)t;
            float z = (Dv - mu) / 1.25f;
            float v = expf(-(z*z));
            sfp[warp][t][lane] = pack2(v, v);
        }

        float dX0 = cj.x - ci.x, dX1 = cj.y - ci.y, dX2 = cj.z - ci.z;
        float du0 = Oi[0]*dX0 + Oi[1]*dX1 + Oi[2]*dX2;
        float du1 = Oi[3]*dX0 + Oi[4]*dX1 + Oi[5]*dX2;
        float du2 = Oi[6]*dX0 + Oi[7]*dX1 + Oi[8]*dX2;
        float nn = fmaxf(sqrtf(du0*du0 + du1*du1 + du2*du2), 1e-12f);
        du0 /= nn; du1 /= nn; du2 /= nn;
        sfp[warp][16][lane] = pack2(du0, du0);
        sfp[warp][17][lane] = pack2(du1, du1);
        sfp[warp][18][lane] = pack2(du2, du2);

        float R[3][3];
        #pragma unroll
        for (int ii = 0; ii < 3; ii++)
            #pragma unroll
            for (int mm = 0; mm < 3; mm++)
                R[ii][mm] = Oi[0*3+ii]*Oj[0*3+mm] + Oi[1*3+ii]*Oj[1*3+mm] + Oi[2*3+ii]*Oj[2*3+mm];
        float mx = 0.5f * sqrtf(fabsf(1.f + R[0][0] - R[1][1] - R[2][2]));
        float my = 0.5f * sqrtf(fabsf(1.f - R[0][0] + R[1][1] - R[2][2]));
        float mz = 0.5f * sqrtf(fabsf(1.f - R[0][0] - R[1][1] + R[2][2]));
        float qx = sgnf(R[2][1] - R[1][2]) * mx;
        float qy = sgnf(R[0][2] - R[2][0]) * my;
        float qz = sgnf(R[1][0] - R[0][1]) * mz;
        float qw = sqrtf(fmaxf(1.f + R[0][0] + R[1][1] + R[2][2], 0.f)) * 0.5f;
        float qn = fmaxf(sqrtf(qx*qx + qy*qy + qz*qz + qw*qw), 1e-12f);
        qx /= qn; qy /= qn; qz /= qn; qw /= qn;
        sfp[warp][19][lane] = pack2(qx, qx);
        sfp[warp][20][lane] = pack2(qy, qy);
        sfp[warp][21][lane] = pack2(qz, qz);
        sfp[warp][22][lane] = pack2(qw, qw);

        int dd = res[nj] - res[node] + 32;
        dd = dd < 0 ? 0 : (dd > 64 ? 64 : dd);
        int same = (chn[nj] == chn[node]) ? 1 : 0;
        sedd[warp][lane] = dd | (same << 8);
    }

    // ---- weights into registers (this lane's 4 channels) ----
    unsigned long long wlo[23], whi[23];
    #pragma unroll
    for (int f = 0; f < 23; f++) {
        ulonglong2 wv = ((const ulonglong2*)(We + (16 + f)*EDGEF))[lane];
        wlo[f] = wv.x; whi[f] = wv.y;
    }
    const float4 bec  = ((const float4*)be)[lane];
    const float4 gec  = ((const float4*)ge)[lane];
    const float4 bnec = ((const float4*)bne)[lane];
    const unsigned long long bec01 = pack2(bec.x, bec.y);
    const unsigned long long bec23 = pack2(bec.z, bec.w);
    __syncwarp();

    // ---- phase 2: matvec + LN per edge ----
    for (int k = 0; k < KK; k++) {
        const int edd = sedd[warp][k];
        const int dd = edd & 255;
        const int same = (edd >> 8) & 1;

        ulonglong2 pp = ((const ulonglong2*)g_posproj)[dd*32 + lane];
        ulonglong2 cp = ((const ulonglong2*)g_chainproj)[(same ? 0 : 32) + lane];
        unsigned long long ax = add2(add2(bec01, pp.x), cp.x);
        unsigned long long ay = add2(add2(bec23, pp.y), cp.y);

        #pragma unroll
        for (int f = 0; f < 23; f++) {
            unsigned long long sp = sfp[warp][f][k];   // broadcast
            ax = fma2(sp, wlo[f], ax);
            ay = fma2(sp, whi[f], ay);
        }

        float x0, x1, x2, x3;
        unpack2(ax, x0, x1);
        unpack2(ay, x2, x3);

        float sum = x0 + x1 + x2 + x3;
        #pragma unroll
        for (int o = 16; o > 0; o >>= 1) sum += __shfl_xor_sync(0xffffffffu, sum, o);
        float mean = sum * (1.0f/EDGEF);
        float d0 = x0-mean, d1 = x1-mean, d2 = x2-mean, d3 = x3-mean;
        float vs = d0*d0 + d1*d1 + d2*d2 + d3*d3;
        #pragma unroll
        for (int o = 16; o > 0; o >>= 1) vs += __shfl_xor_sync(0xffffffffu, vs, o);
        float inv = 1.0f / sqrtf(vs * (1.0f/EDGEF) + 1e-5f);
        float4 y;
        y.x = d0*inv*gec.x + bnec.x;
        y.y = d1*inv*gec.y + bnec.y;
        y.z = d2*inv*gec.z + bnec.z;
        y.w = d3*inv*gec.w + bnec.w;
        ((float4*)outE)[((size_t)node*KK + k)*32 + lane] = y;
    }
}

// ============================================================
extern "C" void kernel_launch(void* const* d_in, const int* in_sizes, int n_in,
                              void* d_out, int out_size) {
    const float* X    = (const float*)d_in[0];
    const int*   res  = (const int*)d_in[2];
    const int*   chn  = (const int*)d_in[3];
    const float* Wpe  = (const float*)d_in[4];
    const float* bpe  = (const float*)d_in[5];
    const float* Wch  = (const float*)d_in[6];
    const float* bch  = (const float*)d_in[7];
    const float* Wn   = (const float*)d_in[8];
    const float* bn   = (const float*)d_in[9];
    const float* We   = (const float*)d_in[10];
    const float* be   = (const float*)d_in[11];
    const float* gn   = (const float*)d_in[12];
    const float* bnn  = (const float*)d_in[13];
    const float* gE   = (const float*)d_in[14];
    const float* bnE  = (const float*)d_in[15];

    float* out = (float*)d_out;
    const size_t VSZ = (size_t)BB*LL*NODEF;       // 1,048,576
    const size_t ESZ = (size_t)BB*LL*KK*EDGEF;    // 31,457,280
    float* outV    = out;
    float* outE    = out + VSZ;
    float* outIdxF = out + VSZ + ESZ;

    pack_kernel<<<(BB*LL + 255)/256, 256>>>(X);
    proj_kernel<<<67, 128>>>(Wpe, bpe, Wch, bch, We);
    node_kernel<<<BB*LL/4, 128>>>(X, Wn, bn, gn, bnn, outV);
    topk_kernel<<<BB*LL/QPB, 256>>>(outIdxF);
    edge_kernel<<<BB*LL/4, 128>>>(res, chn, We, be, gE, bnE, outE);
}